// round 4
// baseline (speedup 1.0000x reference)
#include <cuda_runtime.h>
#include <cstdint>

// Problem shape (fixed): B=32, Q=512, K=512, D=1024
#define NB   32
#define NQ   512
#define NK   512
#define ND   1024

#define BM 128
#define BN 128
#define BK 16

#define NEG_INF (__int_as_float(0xff800000))

// packed fp32x2 helpers (sm_103a)
#define PACK_F32X2(d, x) asm("mov.b64 %0, {%1, %1};" : "=l"(d) : "f"(x))
#define UNPACK_F32X2(lo, hi, v) asm("mov.b64 {%0, %1}, %2;" : "=f"(lo), "=f"(hi) : "l"(v))
#define FMA_F32X2(acc, a, b) asm("fma.rn.f32x2 %0, %1, %2, %0;" : "+l"(acc) : "l"(a), "l"(b))

// ---------------------------------------------------------------------------
// Kernel 1: batched NT SGEMM  C[b] = Qm[b] (512x1024) * Km[b]^T (1024x512)
// 128x128 block tile, BK=16, 256 threads, 8x8 per-thread microtile,
// double-buffered SMEM, packed f32x2 FMA inner loop.
// ---------------------------------------------------------------------------
__global__ __launch_bounds__(256, 2)
void gemm_nt_kernel(const float* __restrict__ Qm,
                    const float* __restrict__ Km,
                    float* __restrict__ C)
{
    const int b  = blockIdx.z;
    const int m0 = blockIdx.y * BM;
    const int n0 = blockIdx.x * BN;

    const float* Ab = Qm + (size_t)b * NQ * ND + (size_t)m0 * ND;
    const float* Bb = Km + (size_t)b * NK * ND + (size_t)n0 * ND;
    float*       Cb = C  + (size_t)b * NQ * NK;

    __shared__ __align__(16) float As[2][BK][BM + 4];
    __shared__ __align__(16) float Bs[2][BK][BM + 4];

    const int tid = threadIdx.x;
    const int tx  = tid & 15;   // column group (8 cols)
    const int ty  = tid >> 4;   // row group    (8 rows)

    // global tile loads: each thread fetches 2 float4 from A and 2 from B
    const int lrow = tid >> 2;  // 0..63
    const int lc4  = tid & 3;   // which float4 within the 16-wide k chunk

    unsigned long long acc[8][4];
#pragma unroll
    for (int i = 0; i < 8; i++)
#pragma unroll
        for (int j = 0; j < 4; j++) acc[i][j] = 0ULL;

    float4 avA0, avA1, avB0, avB1;

    auto ldg = [&](int kt) {
        const float* a0 = Ab + (size_t)lrow * ND + kt * BK + lc4 * 4;
        const float* b0 = Bb + (size_t)lrow * ND + kt * BK + lc4 * 4;
        avA0 = *(const float4*)(a0);
        avA1 = *(const float4*)(a0 + 64 * ND);
        avB0 = *(const float4*)(b0);
        avB1 = *(const float4*)(b0 + 64 * ND);
    };
    auto sts = [&](int buf) {
#pragma unroll
        for (int j = 0; j < 4; j++) {
            As[buf][lc4 * 4 + j][lrow]      = ((const float*)&avA0)[j];
            As[buf][lc4 * 4 + j][lrow + 64] = ((const float*)&avA1)[j];
            Bs[buf][lc4 * 4 + j][lrow]      = ((const float*)&avB0)[j];
            Bs[buf][lc4 * 4 + j][lrow + 64] = ((const float*)&avB1)[j];
        }
    };

    ldg(0);
    sts(0);
    __syncthreads();

    const int NKT = ND / BK;  // 64 k-tiles
    for (int kt = 0; kt < NKT; kt++) {
        const int buf = kt & 1;
        if (kt + 1 < NKT) ldg(kt + 1);

#pragma unroll
        for (int k = 0; k < BK; k++) {
            float4 a0 = *(const float4*)&As[buf][k][ty * 8];
            float4 a1 = *(const float4*)&As[buf][k][ty * 8 + 4];
            const unsigned long long* bp =
                (const unsigned long long*)&Bs[buf][k][tx * 8];
            unsigned long long b0 = bp[0], b1 = bp[1], b2 = bp[2], b3 = bp[3];

            float af[8] = {a0.x, a0.y, a0.z, a0.w, a1.x, a1.y, a1.z, a1.w};
#pragma unroll
            for (int i = 0; i < 8; i++) {
                unsigned long long ai;
                PACK_F32X2(ai, af[i]);
                FMA_F32X2(acc[i][0], ai, b0);
                FMA_F32X2(acc[i][1], ai, b1);
                FMA_F32X2(acc[i][2], ai, b2);
                FMA_F32X2(acc[i][3], ai, b3);
            }
        }

        if (kt + 1 < NKT) sts((kt + 1) & 1);
        __syncthreads();
    }

    // epilogue: write raw logits
#pragma unroll
    for (int i = 0; i < 8; i++) {
        float o[8];
#pragma unroll
        for (int j = 0; j < 4; j++) {
            UNPACK_F32X2(o[2 * j], o[2 * j + 1], acc[i][j]);
        }
        float* cp = Cb + (size_t)(m0 + ty * 8 + i) * NK + n0 + tx * 8;
        ((float4*)cp)[0] = make_float4(o[0], o[1], o[2], o[3]);
        ((float4*)cp)[1] = make_float4(o[4], o[5], o[6], o[7]);
    }
}

// ---------------------------------------------------------------------------
// Kernel 2: fused key-mask + softmax + logsumexp->sigmoid confidence.
// One warp per (b,q) row of 512 logits. 8 warps (256 threads) per block.
// In-place on the attn buffer.
// ---------------------------------------------------------------------------
__global__ __launch_bounds__(256)
void softmax_mask_kernel(float* __restrict__ attn,
                         float* __restrict__ conf,
                         const float* __restrict__ keys,
                         const float* __restrict__ tptr,
                         const float* __restrict__ bptr,
                         int writeConf)
{
    const int lane = threadIdx.x & 31;
    const int w    = threadIdx.x >> 5;
    const int row  = blockIdx.x * 8 + w;          // 0 .. B*Q-1
    const int b    = row >> 9;                    // row / 512

    float* rp = attn + (size_t)row * NK;
    const float* kp = keys + (size_t)b * NK * ND;

    float x[16];
#pragma unroll
    for (int i = 0; i < 16; i++) {
        const int k = i * 32 + lane;
        float v  = rp[k];
        float k0 = __ldg(kp + (size_t)k * ND);    // keys[b,k,0]
        x[i] = (k0 == 0.0f) ? NEG_INF : v;
    }

    // row max
    float m = x[0];
#pragma unroll
    for (int i = 1; i < 16; i++) m = fmaxf(m, x[i]);
#pragma unroll
    for (int o = 16; o > 0; o >>= 1)
        m = fmaxf(m, __shfl_xor_sync(0xffffffffu, m, o));

    // exp and sum
    float e[16];
    float s = 0.0f;
#pragma unroll
    for (int i = 0; i < 16; i++) {
        e[i] = expf(x[i] - m);
        s += e[i];
    }
#pragma unroll
    for (int o = 16; o > 0; o >>= 1)
        s += __shfl_xor_sync(0xffffffffu, s, o);

    const float inv = 1.0f / s;
#pragma unroll
    for (int i = 0; i < 16; i++) {
        const int k = i * 32 + lane;
        rp[k] = e[i] * inv;
    }

    if (lane == 0 && writeConf) {
        const float lse  = m + logf(s);
        const float temp = *tptr;
        const float bia  = *bptr;
        const float z    = (lse + bia) * temp;
        conf[row] = 1.0f / (1.0f + expf(-z));
    }
}

// ---------------------------------------------------------------------------
extern "C" void kernel_launch(void* const* d_in, const int* in_sizes, int n_in,
                              void* d_out, int out_size)
{
    const float* q  = (const float*)d_in[0];
    const float* k  = (const float*)d_in[1];
    const float* t  = (const float*)d_in[2];
    const float* bi = (const float*)d_in[3];

    float* attn = (float*)d_out;
    const long long attnElems = (long long)NB * NQ * NK;       // 8388608
    const int writeConf = (out_size >= attnElems + NB * NQ) ? 1 : 0;
    float* conf = attn + attnElems;

    dim3 grid(NK / BN, NQ / BM, NB);        // (4, 4, 32)
    gemm_nt_kernel<<<grid, 256>>>(q, k, attn);

    softmax_mask_kernel<<<(NB * NQ) / 8, 256>>>(attn, conf, k, t, bi, writeConf);
}

// round 6
// speedup vs baseline: 1.9187x; 1.9187x over previous
#include <cuda_runtime.h>
#include <cuda_fp16.h>
#include <cstdint>

// Problem shape (fixed): B=32, Q=512, K=512, D=1024
#define NB   32
#define NQ   512
#define NK   512
#define ND   1024

#define BM 128
#define BN 128
#define KC 32                  // K elements per chunk
#define NCHUNK (ND / KC)       // 32
#define THREADS 256

#define ROWB32 18              // b32 per SMEM tile row (16 data + 2 pad) = 72B
#define TILE_B32 (128 * ROWB32)            // one 128x32 fp16x2 tile
#define STAGE_B32 (4 * TILE_B32)           // Ahi | Alo | Bhi | Blo
#define SMEM_B32 (2 * STAGE_B32)
#define SMEM_BYTES (SMEM_B32 * 4)          // 73728

#define AHI 0
#define ALO TILE_B32
#define BHI (2 * TILE_B32)
#define BLO (3 * TILE_B32)

#define NEG_INF (__int_as_float(0xff800000))

// fp16x2 scale by 2^-11 (exact exponent shift): half(2^-11) = 0x1000
#define H2_SCALE_DOWN 0x10001000u

__device__ __forceinline__ uint32_t pack_hi2(float x, float y) {
    __half2 h = __floats2half2_rn(x, y);
    return *reinterpret_cast<uint32_t*>(&h);
}
__device__ __forceinline__ uint32_t pack_lo2(float x, float y, uint32_t hi) {
    __half2 h = *reinterpret_cast<__half2*>(&hi);
    float2 hf = __half22float2(h);
    __half2 l = __floats2half2_rn((x - hf.x) * 2048.0f, (y - hf.y) * 2048.0f);
    return *reinterpret_cast<uint32_t*>(&l);
}
__device__ __forceinline__ uint32_t hmul2(uint32_t a, uint32_t s) {
    uint32_t r;
    asm("mul.f16x2 %0, %1, %2;" : "=r"(r) : "r"(a), "r"(s));
    return r;
}

#define MMA161616(c, a0, a1, a2, a3, b0, b1)                                     \
    asm volatile(                                                                \
        "mma.sync.aligned.m16n8k16.row.col.f32.f16.f16.f32 "                     \
        "{%0,%1,%2,%3}, {%4,%5,%6,%7}, {%8,%9}, {%0,%1,%2,%3};"                  \
        : "+f"((c)[0]), "+f"((c)[1]), "+f"((c)[2]), "+f"((c)[3])                 \
        : "r"(a0), "r"(a1), "r"(a2), "r"(a3), "r"(b0), "r"(b1))

// ---------------------------------------------------------------------------
// Kernel 1: batched NT GEMM, fp32 emulated via 3x fp16 mma.sync.
// C[b] = Qm[b](512x1024) * Km[b]^T.  128x128 tile, KC=32 chunks,
// double-buffered SMEM, 8 warps each computing a 64x32 warp tile.
// ---------------------------------------------------------------------------
__global__ __launch_bounds__(THREADS)
void gemm_hmma_kernel(const float* __restrict__ Qm,
                      const float* __restrict__ Km,
                      float* __restrict__ C)
{
    extern __shared__ __align__(16) uint32_t s[];

    const int tid  = threadIdx.x;
    const int wid  = tid >> 5;
    const int lane = tid & 31;
    const int gid  = lane >> 2;       // group id (0..7)
    const int tig  = lane & 3;        // thread in group

    const int wm = wid & 1;           // warp m (0..1) -> 64 rows
    const int wn = wid >> 1;          // warp n (0..3) -> 32 cols

    const int b  = blockIdx.z;
    const int m0 = blockIdx.y * BM;
    const int n0 = blockIdx.x * BN;

    const float* Ab = Qm + (size_t)b * NQ * ND + (size_t)m0 * ND;
    const float* Bb = Km + (size_t)b * NK * ND + (size_t)n0 * ND;
    float*       Cb = C  + (size_t)b * NQ * NK;

    // accumulators: 4 mtiles x 4 ntiles x 4 f32
    float acc[4][4][4];
#pragma unroll
    for (int i = 0; i < 4; i++)
#pragma unroll
        for (int j = 0; j < 4; j++)
#pragma unroll
            for (int k = 0; k < 4; k++) acc[i][j][k] = 0.0f;

    // global load geometry: per thread 4 float4 of A + 4 of B per chunk
    // f = tid + i*256 ; row = f>>3 (0..127), c4 = f&7 (float4 within 32-wide row)
    float4 va[4], vb[4];
#pragma unroll
    for (int i = 0; i < 4; i++) {
        const int f = tid + i * 256;
        const int row = f >> 3, c4 = f & 7;
        va[i] = *(const float4*)(Ab + (size_t)row * ND + c4 * 4);
        vb[i] = *(const float4*)(Bb + (size_t)row * ND + c4 * 4);
    }

    auto sts_chunk = [&](int buf) {
        uint32_t* st = s + buf * STAGE_B32;
#pragma unroll
        for (int i = 0; i < 4; i++) {
            const int f = tid + i * 256;
            const int row = f >> 3, c4 = f & 7;
            const int idx = row * ROWB32 + c4 * 2;
            uint32_t ah0 = pack_hi2(va[i].x, va[i].y);
            uint32_t ah1 = pack_hi2(va[i].z, va[i].w);
            uint32_t al0 = pack_lo2(va[i].x, va[i].y, ah0);
            uint32_t al1 = pack_lo2(va[i].z, va[i].w, ah1);
            uint32_t bh0 = pack_hi2(vb[i].x, vb[i].y);
            uint32_t bh1 = pack_hi2(vb[i].z, vb[i].w);
            uint32_t bl0 = pack_lo2(vb[i].x, vb[i].y, bh0);
            uint32_t bl1 = pack_lo2(vb[i].z, vb[i].w, bh1);
            *(uint2*)(st + AHI + idx) = make_uint2(ah0, ah1);
            *(uint2*)(st + ALO + idx) = make_uint2(al0, al1);
            *(uint2*)(st + BHI + idx) = make_uint2(bh0, bh1);
            *(uint2*)(st + BLO + idx) = make_uint2(bl0, bl1);
        }
    };

    sts_chunk(0);
    __syncthreads();

    const int arow0 = wm * 64 + gid;      // A fragment base row
    const int brow0 = wn * 32 + gid;      // B fragment base row

    for (int kc = 0; kc < NCHUNK; kc++) {
        const int buf = kc & 1;
        const uint32_t* sa = s + buf * STAGE_B32;

        // prefetch next chunk
        if (kc + 1 < NCHUNK) {
#pragma unroll
            for (int i = 0; i < 4; i++) {
                const int f = tid + i * 256;
                const int row = f >> 3, c4 = f & 7;
                va[i] = *(const float4*)(Ab + (size_t)row * ND + (kc + 1) * KC + c4 * 4);
                vb[i] = *(const float4*)(Bb + (size_t)row * ND + (kc + 1) * KC + c4 * 4);
            }
        }

#pragma unroll
        for (int ks = 0; ks < 2; ks++) {
            const int kb = ks * 8 + tig;

            // ---- load hi fragments ----
            uint32_t ah[4][4], bh[4][2];
#pragma unroll
            for (int mt = 0; mt < 4; mt++) {
                const int r = (arow0 + mt * 16) * ROWB32;
                ah[mt][0] = sa[AHI + r + kb];
                ah[mt][1] = sa[AHI + r + 8 * ROWB32 + kb];
                ah[mt][2] = sa[AHI + r + kb + 4];
                ah[mt][3] = sa[AHI + r + 8 * ROWB32 + kb + 4];
            }
#pragma unroll
            for (int nt = 0; nt < 4; nt++) {
                const int r = (brow0 + nt * 8) * ROWB32;
                bh[nt][0] = sa[BHI + r + kb];
                bh[nt][1] = sa[BHI + r + kb + 4];
            }
            // pass 1: hi x hi
#pragma unroll
            for (int mt = 0; mt < 4; mt++)
#pragma unroll
                for (int nt = 0; nt < 4; nt++)
                    MMA161616(acc[mt][nt], ah[mt][0], ah[mt][1], ah[mt][2], ah[mt][3],
                              bh[nt][0], bh[nt][1]);

            // pass 2: (hi_a * 2^-11) x lo_b'
            uint32_t as[4][4], bl[4][2];
#pragma unroll
            for (int mt = 0; mt < 4; mt++)
#pragma unroll
                for (int q = 0; q < 4; q++)
                    as[mt][q] = hmul2(ah[mt][q], H2_SCALE_DOWN);
#pragma unroll
            for (int nt = 0; nt < 4; nt++) {
                const int r = (brow0 + nt * 8) * ROWB32;
                bl[nt][0] = sa[BLO + r + kb];
                bl[nt][1] = sa[BLO + r + kb + 4];
            }
#pragma unroll
            for (int mt = 0; mt < 4; mt++)
#pragma unroll
                for (int nt = 0; nt < 4; nt++)
                    MMA161616(acc[mt][nt], as[mt][0], as[mt][1], as[mt][2], as[mt][3],
                              bl[nt][0], bl[nt][1]);

            // pass 3: lo_a' x (hi_b * 2^-11)
            uint32_t al[4][4], bs[4][2];
#pragma unroll
            for (int mt = 0; mt < 4; mt++) {
                const int r = (arow0 + mt * 16) * ROWB32;
                al[mt][0] = sa[ALO + r + kb];
                al[mt][1] = sa[ALO + r + 8 * ROWB32 + kb];
                al[mt][2] = sa[ALO + r + kb + 4];
                al[mt][3] = sa[ALO + r + 8 * ROWB32 + kb + 4];
            }
#pragma unroll
            for (int nt = 0; nt < 4; nt++) {
                bs[nt][0] = hmul2(bh[nt][0], H2_SCALE_DOWN);
                bs[nt][1] = hmul2(bh[nt][1], H2_SCALE_DOWN);
            }
#pragma unroll
            for (int mt = 0; mt < 4; mt++)
#pragma unroll
                for (int nt = 0; nt < 4; nt++)
                    MMA161616(acc[mt][nt], al[mt][0], al[mt][1], al[mt][2], al[mt][3],
                              bs[nt][0], bs[nt][1]);
        }

        if (kc + 1 < NCHUNK) sts_chunk(buf ^ 1);
        __syncthreads();
    }

    // epilogue: C fragment rows gid / gid+8, cols tig*2 .. tig*2+1
#pragma unroll
    for (int mt = 0; mt < 4; mt++) {
        const int mrow = m0 + wm * 64 + mt * 16 + gid;
#pragma unroll
        for (int nt = 0; nt < 4; nt++) {
            const int col = n0 + wn * 32 + nt * 8 + tig * 2;
            float* cp0 = Cb + (size_t)mrow * NK + col;
            float* cp1 = Cb + (size_t)(mrow + 8) * NK + col;
            *(float2*)cp0 = make_float2(acc[mt][nt][0], acc[mt][nt][1]);
            *(float2*)cp1 = make_float2(acc[mt][nt][2], acc[mt][nt][3]);
        }
    }
}

// ---------------------------------------------------------------------------
// Kernel 2: fused key-mask + softmax + logsumexp->sigmoid confidence.
// One warp per (b,q) row; key mask staged through SMEM once per block.
// ---------------------------------------------------------------------------
__global__ __launch_bounds__(256)
void softmax_mask_kernel(float* __restrict__ attn,
                         float* __restrict__ conf,
                         const float* __restrict__ keys,
                         const float* __restrict__ tptr,
                         const float* __restrict__ bptr,
                         int writeConf)
{
    __shared__ float k0s[NK];

    const int lane = threadIdx.x & 31;
    const int w    = threadIdx.x >> 5;
    const int row0 = blockIdx.x * 8;
    const int b    = row0 >> 9;                    // all 8 rows share a batch

    const float* kp = keys + (size_t)b * NK * ND;
    for (int k = threadIdx.x; k < NK; k += 256)
        k0s[k] = __ldg(kp + (size_t)k * ND);       // keys[b,k,0]
    __syncthreads();

    const int row = row0 + w;
    float* rp = attn + (size_t)row * NK;

    float x[16];
#pragma unroll
    for (int i = 0; i < 16; i++) {
        const int k = i * 32 + lane;
        float v = rp[k];
        x[i] = (k0s[k] == 0.0f) ? NEG_INF : v;
    }

    float m = x[0];
#pragma unroll
    for (int i = 1; i < 16; i++) m = fmaxf(m, x[i]);
#pragma unroll
    for (int o = 16; o > 0; o >>= 1)
        m = fmaxf(m, __shfl_xor_sync(0xffffffffu, m, o));

    float e[16];
    float sum = 0.0f;
#pragma unroll
    for (int i = 0; i < 16; i++) {
        e[i] = expf(x[i] - m);
        sum += e[i];
    }
#pragma unroll
    for (int o = 16; o > 0; o >>= 1)
        sum += __shfl_xor_sync(0xffffffffu, sum, o);

    const float inv = 1.0f / sum;
#pragma unroll
    for (int i = 0; i < 16; i++) {
        const int k = i * 32 + lane;
        rp[k] = e[i] * inv;
    }

    if (lane == 0 && writeConf) {
        const float lse  = m + logf(sum);
        const float temp = *tptr;
        const float bia  = *bptr;
        const float z    = (lse + bia) * temp;
        conf[row] = 1.0f / (1.0f + expf(-z));
    }
}

// ---------------------------------------------------------------------------
extern "C" void kernel_launch(void* const* d_in, const int* in_sizes, int n_in,
                              void* d_out, int out_size)
{
    const float* q  = (const float*)d_in[0];
    const float* k  = (const float*)d_in[1];
    const float* t  = (const float*)d_in[2];
    const float* bi = (const float*)d_in[3];

    float* attn = (float*)d_out;
    const long long attnElems = (long long)NB * NQ * NK;       // 8388608
    const int writeConf = (out_size >= attnElems + NB * NQ) ? 1 : 0;
    float* conf = attn + attnElems;

    static int smemSet = 0;
    if (!smemSet) {
        cudaFuncSetAttribute(gemm_hmma_kernel,
                             cudaFuncAttributeMaxDynamicSharedMemorySize, SMEM_BYTES);
        smemSet = 1;
    }

    dim3 grid(NK / BN, NQ / BM, NB);        // (4, 4, 32)
    gemm_hmma_kernel<<<grid, THREADS, SMEM_BYTES>>>(q, k, attn);

    softmax_mask_kernel<<<(NB * NQ) / 8, 256>>>(attn, conf, k, t, bi, writeConf);
}